// round 1
// baseline (speedup 1.0000x reference)
#include <cuda_runtime.h>

// ---------------------------------------------------------------------------
// GINE encoder, fp32, feature dim padded 300 -> 320 (pad cols are identically 0)
// ---------------------------------------------------------------------------

#define D0      300
#define DP      320
#define NMAX    100000
#define EMAX    250000
#define GMAX    4096
#define NLAYER  5
#define BN_EPS  1e-5f

// scratch (static device globals; no runtime allocation)
__device__ float g_h  [(size_t)NMAX * DP];
__device__ float g_agg[(size_t)NMAX * DP];
__device__ float g_t  [(size_t)NMAX * DP];
__device__ float g_e  [(size_t)EMAX * DP];
__device__ float g_tmp[(size_t)EMAX * DP];
__device__ float g_pool[(size_t)GMAX * DP];
__device__ float g_cnt[GMAX];
__device__ float g_inv[GMAX];
__device__ float g_sum[DP];
__device__ float g_sq [DP];
__device__ float g_scale[DP];
__device__ float g_shift[DP];

// ---------------------------------------------------------------------------
__global__ void k_fill0(float4* p, int n4) {
    int i = blockIdx.x * blockDim.x + threadIdx.x;
    if (i < n4) p[i] = make_float4(0.f, 0.f, 0.f, 0.f);
}

__global__ void k_zerostats() {
    int j = threadIdx.x;
    g_sum[j] = 0.f;
    g_sq[j]  = 0.f;
}

// node hidden: relu([chir,fc] @ nW1 + nb1)  -> out [N,DP] (pads zero)
__global__ void k_node_hidden(const float* __restrict__ ch, const float* __restrict__ fc,
                              const float* __restrict__ W,  const float* __restrict__ b,
                              float* __restrict__ out, int N) {
    int idx = blockIdx.x * blockDim.x + threadIdx.x;
    if (idx >= N * 80) return;
    int i = idx / 80;
    int c = (idx - i * 80) * 4;
    float a0 = ch[i], a1 = fc[i];
    float4 o;
    float* op = &o.x;
#pragma unroll
    for (int j = 0; j < 4; j++) {
        int col = c + j;
        float v = 0.f;
        if (col < D0)
            v = fmaxf(fmaf(a0, W[col], fmaf(a1, W[D0 + col], b[col])), 0.f);
        op[j] = v;
    }
    *(float4*)(out + (size_t)i * DP + c) = o;
}

// edge hidden: relu(edge_attr @ eW1 + eb1) -> out [E,DP]
__global__ void k_edge_hidden(const float* __restrict__ ea,
                              const float* __restrict__ W, const float* __restrict__ b,
                              float* __restrict__ out, int E) {
    int idx = blockIdx.x * blockDim.x + threadIdx.x;
    if (idx >= E * 80) return;
    int i = idx / 80;
    int c = (idx - i * 80) * 4;
    float a0 = ea[(size_t)i * 3 + 0];
    float a1 = ea[(size_t)i * 3 + 1];
    float a2 = ea[(size_t)i * 3 + 2];
    float4 o;
    float* op = &o.x;
#pragma unroll
    for (int j = 0; j < 4; j++) {
        int col = c + j;
        float v = 0.f;
        if (col < D0)
            v = fmaxf(fmaf(a0, W[col], fmaf(a1, W[D0 + col], fmaf(a2, W[2 * D0 + col], b[col]))), 0.f);
        op[j] = v;
    }
    *(float4*)(out + (size_t)i * DP + c) = o;
}

// one warp per edge: agg[dst] += relu(h[src] + e[edge])
__global__ void k_scatter(const int* __restrict__ src, const int* __restrict__ dst, int E) {
    int w = (blockIdx.x * blockDim.x + threadIdx.x) >> 5;
    int lane = threadIdx.x & 31;
    if (w >= E) return;
    int s = src[w], d = dst[w];
    const float4* hp = (const float4*)(g_h + (size_t)s * DP);
    const float4* ep = (const float4*)(g_e + (size_t)w * DP);
    float* ap = g_agg + (size_t)d * DP;
    for (int c = lane; c < DP / 4; c += 32) {
        float4 hv = hp[c], ev = ep[c];
        float mx = fmaxf(hv.x + ev.x, 0.f);
        float my = fmaxf(hv.y + ev.y, 0.f);
        float mz = fmaxf(hv.z + ev.z, 0.f);
        float mw = fmaxf(hv.w + ev.w, 0.f);
        atomicAdd(ap + 4 * c + 0, mx);
        atomicAdd(ap + 4 * c + 1, my);
        atomicAdd(ap + 4 * c + 2, mz);
        atomicAdd(ap + 4 * c + 3, mw);
    }
}

__global__ void k_bnprep(const float* __restrict__ gamma, const float* __restrict__ beta, float invN) {
    int j = threadIdx.x;  // 0..DP-1
    float mu  = g_sum[j] * invN;
    float var = g_sq[j] * invN - mu * mu;
    float inv = rsqrtf(var + BN_EPS);
    float ga = (j < D0) ? gamma[j] : 0.f;
    float be = (j < D0) ? beta[j]  : 0.f;
    float sc = ga * inv;
    g_scale[j] = sc;
    g_shift[j] = be - mu * sc;
}

// h = relu(agg * scale + shift)
__global__ void k_bnapply(int N) {
    int idx = blockIdx.x * blockDim.x + threadIdx.x;
    if (idx >= N * 80) return;
    int i = idx / 80;
    int c = (idx - i * 80) * 4;
    float4 v = *(const float4*)(g_agg + (size_t)i * DP + c);
    v.x = fmaxf(fmaf(v.x, g_scale[c + 0], g_shift[c + 0]), 0.f);
    v.y = fmaxf(fmaf(v.y, g_scale[c + 1], g_shift[c + 1]), 0.f);
    v.z = fmaxf(fmaf(v.z, g_scale[c + 2], g_shift[c + 2]), 0.f);
    v.w = fmaxf(fmaf(v.w, g_scale[c + 3], g_shift[c + 3]), 0.f);
    *(float4*)(g_h + (size_t)i * DP + c) = v;
}

__global__ void k_count(const int* __restrict__ batch, int N) {
    int i = blockIdx.x * blockDim.x + threadIdx.x;
    if (i < N) atomicAdd(&g_cnt[batch[i]], 1.f);
}

__global__ void k_inv(int G) {
    int i = blockIdx.x * blockDim.x + threadIdx.x;
    if (i < G) g_inv[i] = 1.f / fmaxf(g_cnt[i], 1.f);
}

__global__ void k_pool(const int* __restrict__ batch, int N) {
    int idx = blockIdx.x * blockDim.x + threadIdx.x;
    if (idx >= N * 80) return;
    int i = idx / 80;
    int c = (idx - i * 80) * 4;
    int g = batch[i];
    float4 v = *(const float4*)(g_h + (size_t)i * DP + c);
    float* pp = g_pool + (size_t)g * DP + c;
    atomicAdd(pp + 0, v.x);
    atomicAdd(pp + 1, v.y);
    atomicAdd(pp + 2, v.z);
    atomicAdd(pp + 3, v.w);
}

// ---------------------------------------------------------------------------
// GEMM: C[M,DP] = epi( (A (+A2)) (*rowscale) @ W[300,300] + bias )
// tiles: 128x128x16, 8x8 micro, 256 threads
// EPI: 0 = bias, 1 = bias+relu, 2 = bias+emb gather, 3 = bias+BN stats,
//      4 = bias, write d_out with stride 300 (cols < 300 only)
// ---------------------------------------------------------------------------
#define BMm 128
#define BNn 128
#define BKk 16
#define ASTR 132

template <int EPI>
__global__ __launch_bounds__(256)
void k_gemm(const float* __restrict__ A, const float* __restrict__ A2,
            const float* __restrict__ rowscale,
            const float* __restrict__ W, const float* __restrict__ bias,
            float* __restrict__ C, int M,
            const int* __restrict__ zidx, const float* __restrict__ emb) {
    __shared__ float As[BKk * ASTR];
    __shared__ float Bs[BKk * BNn];

    const int tid = threadIdx.x;
    const int tx = tid & 15;
    const int ty = tid >> 4;
    const int row0 = blockIdx.y * BMm;
    const int col0 = blockIdx.x * BNn;

    float acc[8][8];
#pragma unroll
    for (int i = 0; i < 8; i++)
#pragma unroll
        for (int j = 0; j < 8; j++) acc[i][j] = 0.f;

    const int a_r = tid >> 2;
    const int a_c = (tid & 3) << 2;
    const int b_k = tid >> 5;
    const int b_c = (tid & 31) << 2;

    for (int k0 = 0; k0 < DP; k0 += BKk) {
#pragma unroll
        for (int h = 0; h < 2; h++) {
            int r = a_r + h * 64;
            int grow = row0 + r;
            float4 v = make_float4(0.f, 0.f, 0.f, 0.f);
            if (grow < M) {
                v = *(const float4*)(A + (size_t)grow * DP + (k0 + a_c));
                if (A2) {
                    float4 u = *(const float4*)(A2 + (size_t)grow * DP + (k0 + a_c));
                    v.x += u.x; v.y += u.y; v.z += u.z; v.w += u.w;
                }
                if (rowscale) {
                    float s = rowscale[grow];
                    v.x *= s; v.y *= s; v.z *= s; v.w *= s;
                }
            }
            As[(a_c + 0) * ASTR + r] = v.x;
            As[(a_c + 1) * ASTR + r] = v.y;
            As[(a_c + 2) * ASTR + r] = v.z;
            As[(a_c + 3) * ASTR + r] = v.w;
        }
#pragma unroll
        for (int h = 0; h < 2; h++) {
            int kr = b_k + h * 8;
            int gk = k0 + kr;
            int gc = col0 + b_c;
            float4 v = make_float4(0.f, 0.f, 0.f, 0.f);
            if (gk < D0 && gc < D0)
                v = *(const float4*)(W + (size_t)gk * D0 + gc);
            *(float4*)&Bs[kr * BNn + b_c] = v;
        }
        __syncthreads();
#pragma unroll
        for (int kk = 0; kk < BKk; kk++) {
            float af[8], bf[8];
            float4 t0 = *(const float4*)&As[kk * ASTR + ty * 8];
            float4 t1 = *(const float4*)&As[kk * ASTR + ty * 8 + 4];
            af[0] = t0.x; af[1] = t0.y; af[2] = t0.z; af[3] = t0.w;
            af[4] = t1.x; af[5] = t1.y; af[6] = t1.z; af[7] = t1.w;
            float4 u0 = *(const float4*)&Bs[kk * BNn + tx * 8];
            float4 u1 = *(const float4*)&Bs[kk * BNn + tx * 8 + 4];
            bf[0] = u0.x; bf[1] = u0.y; bf[2] = u0.z; bf[3] = u0.w;
            bf[4] = u1.x; bf[5] = u1.y; bf[6] = u1.z; bf[7] = u1.w;
#pragma unroll
            for (int i = 0; i < 8; i++)
#pragma unroll
                for (int j = 0; j < 8; j++)
                    acc[i][j] = fmaf(af[i], bf[j], acc[i][j]);
        }
        __syncthreads();
    }

    float bcol[8];
#pragma unroll
    for (int j = 0; j < 8; j++) {
        int c = col0 + tx * 8 + j;
        bcol[j] = (c < D0) ? bias[c] : 0.f;
    }

    float lsum[8], lsq[8];
    if (EPI == 3) {
#pragma unroll
        for (int j = 0; j < 8; j++) { lsum[j] = 0.f; lsq[j] = 0.f; }
    }

#pragma unroll
    for (int i = 0; i < 8; i++) {
        int grow = row0 + ty * 8 + i;
        if (grow >= M) continue;
        int zi = 0;
        if (EPI == 2) zi = zidx[grow];
#pragma unroll
        for (int j = 0; j < 8; j++) {
            int c = col0 + tx * 8 + j;
            float v = acc[i][j] + bcol[j];
            if (EPI == 1) v = fmaxf(v, 0.f);
            if (EPI == 2) { if (c < D0) v += emb[(size_t)zi * D0 + c]; }
            if (EPI == 3) { lsum[j] += v; lsq[j] += v * v; }
            if (EPI == 4) {
                if (c < D0) C[(size_t)grow * D0 + c] = v;
            } else {
                if (c < DP) C[(size_t)grow * DP + c] = v;
            }
        }
    }

    if (EPI == 3) {
        __syncthreads();
        float* r1 = As;   // 2112 floats available, need 2048
        float* r2 = Bs;   // 2048 floats
#pragma unroll
        for (int j = 0; j < 8; j++) {
            r1[ty * BNn + tx * 8 + j] = lsum[j];
            r2[ty * BNn + tx * 8 + j] = lsq[j];
        }
        __syncthreads();
        if (tid < BNn) {
            float s = 0.f, q = 0.f;
#pragma unroll
            for (int t = 0; t < 16; t++) { s += r1[t * BNn + tid]; q += r2[t * BNn + tid]; }
            int c = col0 + tid;
            if (c < DP) {
                atomicAdd(&g_sum[c], s);
                atomicAdd(&g_sq[c], q);
            }
        }
    }
}

static void gemm_launch(int epi, const float* A, const float* A2, const float* rs,
                        const float* W, const float* bias, float* C, int M,
                        const int* z, const float* emb) {
    dim3 grid(3, (M + BMm - 1) / BMm);
    switch (epi) {
        case 0: k_gemm<0><<<grid, 256>>>(A, A2, rs, W, bias, C, M, z, emb); break;
        case 1: k_gemm<1><<<grid, 256>>>(A, A2, rs, W, bias, C, M, z, emb); break;
        case 2: k_gemm<2><<<grid, 256>>>(A, A2, rs, W, bias, C, M, z, emb); break;
        case 3: k_gemm<3><<<grid, 256>>>(A, A2, rs, W, bias, C, M, z, emb); break;
        case 4: k_gemm<4><<<grid, 256>>>(A, A2, rs, W, bias, C, M, z, emb); break;
    }
}

// ---------------------------------------------------------------------------
extern "C" void kernel_launch(void* const* d_in, const int* in_sizes, int n_in,
                              void* d_out, int out_size) {
    const int*   z     = (const int*)d_in[0];
    const float* ch    = (const float*)d_in[1];
    const float* fc    = (const float*)d_in[2];
    const int*   ei    = (const int*)d_in[3];
    const float* ea    = (const float*)d_in[4];
    const int*   batch = (const int*)d_in[5];

    int o = (in_sizes[6] == 1) ? 7 : 6;  // skip num_graphs scalar if present
    const float* atom_emb = (const float*)d_in[o + 0];
    const float* nW1   = (const float*)d_in[o + 1];
    const float* nb1   = (const float*)d_in[o + 2];
    const float* nW2   = (const float*)d_in[o + 3];
    const float* nb2   = (const float*)d_in[o + 4];
    const float* eW1   = (const float*)d_in[o + 5];
    const float* eb1   = (const float*)d_in[o + 6];
    const float* eW2   = (const float*)d_in[o + 7];
    const float* eb2   = (const float*)d_in[o + 8];
    const float* mW1   = (const float*)d_in[o + 9];
    const float* mb1   = (const float*)d_in[o + 10];
    const float* mW2   = (const float*)d_in[o + 11];
    const float* mb2   = (const float*)d_in[o + 12];
    const float* gamma = (const float*)d_in[o + 13];
    const float* beta  = (const float*)d_in[o + 14];
    const float* pW    = (const float*)d_in[o + 15];
    const float* pb    = (const float*)d_in[o + 16];

    int N = in_sizes[0];
    int E = in_sizes[3] / 2;
    int G = out_size / D0;
    const int* src = ei;
    const int* dst = ei + E;

    float *ph, *pagg, *pt, *pe, *ptmp, *ppool, *pcnt, *pinv;
    cudaGetSymbolAddress((void**)&ph,    g_h);
    cudaGetSymbolAddress((void**)&pagg,  g_agg);
    cudaGetSymbolAddress((void**)&pt,    g_t);
    cudaGetSymbolAddress((void**)&pe,    g_e);
    cudaGetSymbolAddress((void**)&ptmp,  g_tmp);
    cudaGetSymbolAddress((void**)&ppool, g_pool);
    cudaGetSymbolAddress((void**)&pcnt,  g_cnt);
    cudaGetSymbolAddress((void**)&pinv,  g_inv);

    int n4 = N * 80;  // float4 count of an [N,DP] buffer

    // node encoder: h = atom_emb[z] + relu(attr@nW1+nb1)@nW2 + nb2
    k_node_hidden<<<(n4 + 255) / 256, 256>>>(ch, fc, nW1, nb1, pt, N);
    gemm_launch(2, pt, nullptr, nullptr, nW2, nb2, ph, N, z, atom_emb);

    // edge encoder: e = relu(edge_attr@eW1+eb1)@eW2 + eb2
    int e4 = E * 80;
    k_edge_hidden<<<(e4 + 255) / 256, 256>>>(ea, eW1, eb1, ptmp, E);
    gemm_launch(0, ptmp, nullptr, nullptr, eW2, eb2, pe, E, nullptr, nullptr);

    for (int l = 0; l < NLAYER; l++) {
        k_fill0<<<(n4 + 255) / 256, 256>>>((float4*)pagg, n4);
        k_scatter<<<(E * 32 + 255) / 256, 256>>>(src, dst, E);
        // t = relu((h + agg) @ mW1[l] + mb1[l])
        gemm_launch(1, ph, pagg, nullptr, mW1 + (size_t)l * D0 * D0, mb1 + (size_t)l * D0,
                    pt, N, nullptr, nullptr);
        k_zerostats<<<1, DP>>>();
        // agg = t @ mW2[l] + mb2[l]  (+ column stats)
        gemm_launch(3, pt, nullptr, nullptr, mW2 + (size_t)l * D0 * D0, mb2 + (size_t)l * D0,
                    pagg, N, nullptr, nullptr);
        k_bnprep<<<1, DP>>>(gamma + (size_t)l * D0, beta + (size_t)l * D0, 1.f / (float)N);
        k_bnapply<<<(n4 + 255) / 256, 256>>>(N);
    }

    // mean pooling + projection
    int g4 = G * 80;
    k_fill0<<<(g4 + 255) / 256, 256>>>((float4*)ppool, g4);
    k_fill0<<<(G / 4 + 255) / 256, 256>>>((float4*)pcnt, G / 4);
    k_count<<<(N + 255) / 256, 256>>>(batch, N);
    k_pool<<<(n4 + 255) / 256, 256>>>(batch, N);
    k_inv<<<(G + 255) / 256, 256>>>(G);
    gemm_launch(4, ppool, nullptr, pinv, pW, pb, (float*)d_out, G, nullptr, nullptr);
}

// round 2
// speedup vs baseline: 2.2949x; 2.2949x over previous
#include <cuda_runtime.h>
#include <cstdint>

// ---------------------------------------------------------------------------
// GINE encoder. GEMMs on tensor pipe via mma.sync tf32; fp32 elsewhere.
// Feature dim padded 300 -> 320 (pad cols identically 0 everywhere).
// ---------------------------------------------------------------------------

#define D0      300
#define DP      320
#define NMAX    100000
#define EMAX    250000
#define GMAX    4096
#define NLAYER  5
#define BN_EPS  1e-5f

__device__ float g_h  [(size_t)NMAX * DP];
__device__ float g_agg[(size_t)NMAX * DP];
__device__ float g_t  [(size_t)NMAX * DP];
__device__ float g_e  [(size_t)EMAX * DP];
__device__ float g_tmp[(size_t)EMAX * DP];
__device__ float g_pool[(size_t)GMAX * DP];
__device__ float g_cnt[GMAX];
__device__ float g_inv[GMAX];
__device__ float g_sum[DP];
__device__ float g_sq [DP];
__device__ float g_scale[DP];
__device__ float g_shift[DP];

// ---------------------------------------------------------------------------
__global__ void k_fill0(float4* p, int n4) {
    int i = blockIdx.x * blockDim.x + threadIdx.x;
    if (i < n4) p[i] = make_float4(0.f, 0.f, 0.f, 0.f);
}

__global__ void k_zerostats() {
    int j = threadIdx.x;
    g_sum[j] = 0.f;
    g_sq[j]  = 0.f;
}

__global__ void k_node_hidden(const float* __restrict__ ch, const float* __restrict__ fc,
                              const float* __restrict__ W,  const float* __restrict__ b,
                              float* __restrict__ out, int N) {
    int idx = blockIdx.x * blockDim.x + threadIdx.x;
    if (idx >= N * 80) return;
    int i = idx / 80;
    int c = (idx - i * 80) * 4;
    float a0 = ch[i], a1 = fc[i];
    float4 o;
    float* op = &o.x;
#pragma unroll
    for (int j = 0; j < 4; j++) {
        int col = c + j;
        float v = 0.f;
        if (col < D0)
            v = fmaxf(fmaf(a0, W[col], fmaf(a1, W[D0 + col], b[col])), 0.f);
        op[j] = v;
    }
    *(float4*)(out + (size_t)i * DP + c) = o;
}

__global__ void k_edge_hidden(const float* __restrict__ ea,
                              const float* __restrict__ W, const float* __restrict__ b,
                              float* __restrict__ out, int E) {
    int idx = blockIdx.x * blockDim.x + threadIdx.x;
    if (idx >= E * 80) return;
    int i = idx / 80;
    int c = (idx - i * 80) * 4;
    float a0 = ea[(size_t)i * 3 + 0];
    float a1 = ea[(size_t)i * 3 + 1];
    float a2 = ea[(size_t)i * 3 + 2];
    float4 o;
    float* op = &o.x;
#pragma unroll
    for (int j = 0; j < 4; j++) {
        int col = c + j;
        float v = 0.f;
        if (col < D0)
            v = fmaxf(fmaf(a0, W[col], fmaf(a1, W[D0 + col], fmaf(a2, W[2 * D0 + col], b[col]))), 0.f);
        op[j] = v;
    }
    *(float4*)(out + (size_t)i * DP + c) = o;
}

// one warp per edge: agg[dst] += relu(h[src] + e[edge]); vectorized REDG
__global__ void k_scatter(const int* __restrict__ src, const int* __restrict__ dst, int E) {
    int w = (blockIdx.x * blockDim.x + threadIdx.x) >> 5;
    int lane = threadIdx.x & 31;
    if (w >= E) return;
    int s = src[w], d = dst[w];
    const float4* hp = (const float4*)(g_h + (size_t)s * DP);
    const float4* ep = (const float4*)(g_e + (size_t)w * DP);
    float* ap = g_agg + (size_t)d * DP;
#pragma unroll
    for (int it = 0; it < 3; it++) {
        int c = lane + it * 32;
        if (c < 75) {  // cols 300..319 are zero; skip
            float4 hv = hp[c], ev = ep[c];
            float x = fmaxf(hv.x + ev.x, 0.f);
            float y = fmaxf(hv.y + ev.y, 0.f);
            float z = fmaxf(hv.z + ev.z, 0.f);
            float v = fmaxf(hv.w + ev.w, 0.f);
            asm volatile("red.global.add.v4.f32 [%0], {%1,%2,%3,%4};"
                         :: "l"(ap + 4 * c), "f"(x), "f"(y), "f"(z), "f"(v) : "memory");
        }
    }
}

// per-column sum / sumsq over X[N,DP]
__global__ void k_stats(const float* __restrict__ X, int N) {
    int col = threadIdx.x;  // 0..DP-1
    int r0 = blockIdx.x * 512;
    int r1 = min(r0 + 512, N);
    float s = 0.f, q = 0.f;
    for (int r = r0; r < r1; r++) {
        float v = X[(size_t)r * DP + col];
        s += v;
        q += v * v;
    }
    atomicAdd(&g_sum[col], s);
    atomicAdd(&g_sq[col], q);
}

__global__ void k_bnprep(const float* __restrict__ gamma, const float* __restrict__ beta, float invN) {
    int j = threadIdx.x;
    float mu  = g_sum[j] * invN;
    float var = g_sq[j] * invN - mu * mu;
    float inv = rsqrtf(var + BN_EPS);
    float ga = (j < D0) ? gamma[j] : 0.f;
    float be = (j < D0) ? beta[j]  : 0.f;
    float sc = ga * inv;
    g_scale[j] = sc;
    g_shift[j] = be - mu * sc;
}

__global__ void k_bnapply(int N) {
    int idx = blockIdx.x * blockDim.x + threadIdx.x;
    if (idx >= N * 80) return;
    int i = idx / 80;
    int c = (idx - i * 80) * 4;
    float4 v = *(const float4*)(g_agg + (size_t)i * DP + c);
    v.x = fmaxf(fmaf(v.x, g_scale[c + 0], g_shift[c + 0]), 0.f);
    v.y = fmaxf(fmaf(v.y, g_scale[c + 1], g_shift[c + 1]), 0.f);
    v.z = fmaxf(fmaf(v.z, g_scale[c + 2], g_shift[c + 2]), 0.f);
    v.w = fmaxf(fmaf(v.w, g_scale[c + 3], g_shift[c + 3]), 0.f);
    *(float4*)(g_h + (size_t)i * DP + c) = v;
}

__global__ void k_count(const int* __restrict__ batch, int N) {
    int i = blockIdx.x * blockDim.x + threadIdx.x;
    if (i < N) atomicAdd(&g_cnt[batch[i]], 1.f);
}

__global__ void k_inv(int G) {
    int i = blockIdx.x * blockDim.x + threadIdx.x;
    if (i < G) g_inv[i] = 1.f / fmaxf(g_cnt[i], 1.f);
}

__global__ void k_pool(const int* __restrict__ batch, int N) {
    int w = (blockIdx.x * blockDim.x + threadIdx.x) >> 5;
    int lane = threadIdx.x & 31;
    if (w >= N) return;
    int g = batch[w];
    const float4* hp = (const float4*)(g_h + (size_t)w * DP);
    float* pp = g_pool + (size_t)g * DP;
#pragma unroll
    for (int it = 0; it < 3; it++) {
        int c = lane + it * 32;
        if (c < 75) {
            float4 v = hp[c];
            asm volatile("red.global.add.v4.f32 [%0], {%1,%2,%3,%4};"
                         :: "l"(pp + 4 * c), "f"(v.x), "f"(v.y), "f"(v.z), "f"(v.w) : "memory");
        }
    }
}

// ---------------------------------------------------------------------------
// Tensor-core GEMM (mma.sync m16n8k8 tf32):
// C[M,*] = epi( ((A (+A2)) (*rowscale)) @ W[300,300] + bias )
// Block 128x128, BK=32, 8 warps (2x4), warp tile 64x32, 16 mma/k-step/warp.
// EPI: 0 = bias      -> C stride DP
//      1 = bias+relu -> C stride DP
//      2 = bias + atom_emb[z] gather -> C stride DP
//      4 = bias      -> C stride 300 (cols<300 only; final output)
// ---------------------------------------------------------------------------
#define BM 128
#define BN 128
#define BK 32

__device__ __forceinline__ float to_tf32(float x) {
    uint32_t y;
    asm("cvt.rna.tf32.f32 %0, %1;" : "=r"(y) : "f"(x));
    return __uint_as_float(y);
}

__device__ __forceinline__ void mma8(float c[4], const uint32_t a[4], const uint32_t b[2]) {
    asm volatile(
        "mma.sync.aligned.m16n8k8.row.col.f32.tf32.tf32.f32 "
        "{%0,%1,%2,%3}, {%4,%5,%6,%7}, {%8,%9}, {%0,%1,%2,%3};"
        : "+f"(c[0]), "+f"(c[1]), "+f"(c[2]), "+f"(c[3])
        : "r"(a[0]), "r"(a[1]), "r"(a[2]), "r"(a[3]), "r"(b[0]), "r"(b[1]));
}

template <int EPI>
__global__ __launch_bounds__(256, 2)
void k_gemm(const float* __restrict__ A, const float* __restrict__ A2,
            const float* __restrict__ rowscale,
            const float* __restrict__ W, const float* __restrict__ bias,
            float* __restrict__ C, int M,
            const int* __restrict__ zidx, const float* __restrict__ emb) {
    __shared__ float As[BM][BK + 4];   // [m][k], stride 36 -> conflict-free frag reads
    __shared__ float Bs[BK][BN + 4];   // [k][n], stride 132 -> conflict-free frag reads

    const int tid = threadIdx.x;
    const int wid = tid >> 5;
    const int lane = tid & 31;
    const int warp_m = wid & 1;        // 2 warps along M
    const int warp_n = wid >> 1;       // 4 warps along N
    const int grp = lane >> 2;         // 0..7
    const int tg  = lane & 3;          // 0..3
    const int row0 = blockIdx.y * BM;
    const int col0 = blockIdx.x * BN;

    float acc[4][4][4];
#pragma unroll
    for (int i = 0; i < 4; i++)
#pragma unroll
        for (int j = 0; j < 4; j++)
#pragma unroll
            for (int k = 0; k < 4; k++) acc[i][j][k] = 0.f;

    for (int k0 = 0; k0 < DP; k0 += BK) {
        // load A tile: 128 rows x 32 k (1024 float4 slots)
#pragma unroll
        for (int it = 0; it < 4; it++) {
            int id = tid + it * 256;
            int r = id >> 3;
            int c4 = (id & 7) * 4;
            int grow = row0 + r;
            float4 v = make_float4(0.f, 0.f, 0.f, 0.f);
            if (grow < M) {
                v = *(const float4*)(A + (size_t)grow * DP + k0 + c4);
                if (A2) {
                    float4 u = *(const float4*)(A2 + (size_t)grow * DP + k0 + c4);
                    v.x += u.x; v.y += u.y; v.z += u.z; v.w += u.w;
                }
                if (rowscale) {
                    float s = rowscale[grow];
                    v.x *= s; v.y *= s; v.z *= s; v.w *= s;
                }
            }
            v.x = to_tf32(v.x); v.y = to_tf32(v.y); v.z = to_tf32(v.z); v.w = to_tf32(v.w);
            *(float4*)&As[r][c4] = v;
        }
        // load B tile: 32 k x 128 n
#pragma unroll
        for (int it = 0; it < 4; it++) {
            int id = tid + it * 256;
            int k = id >> 5;
            int c4 = (id & 31) * 4;
            int gk = k0 + k;
            int gc = col0 + c4;
            float4 v = make_float4(0.f, 0.f, 0.f, 0.f);
            if (gk < D0 && gc < D0)
                v = *(const float4*)(W + (size_t)gk * D0 + gc);
            v.x = to_tf32(v.x); v.y = to_tf32(v.y); v.z = to_tf32(v.z); v.w = to_tf32(v.w);
            *(float4*)&Bs[k][c4] = v;
        }
        __syncthreads();

#pragma unroll
        for (int ks = 0; ks < 4; ks++) {
            const int kk = ks * 8;
            uint32_t a[4][4], b[4][2];
#pragma unroll
            for (int mt = 0; mt < 4; mt++) {
                int m = warp_m * 64 + mt * 16 + grp;
                a[mt][0] = __float_as_uint(As[m][kk + tg]);
                a[mt][1] = __float_as_uint(As[m + 8][kk + tg]);
                a[mt][2] = __float_as_uint(As[m][kk + tg + 4]);
                a[mt][3] = __float_as_uint(As[m + 8][kk + tg + 4]);
            }
#pragma unroll
            for (int nt = 0; nt < 4; nt++) {
                int n = warp_n * 32 + nt * 8 + grp;
                b[nt][0] = __float_as_uint(Bs[kk + tg][n]);
                b[nt][1] = __float_as_uint(Bs[kk + tg + 4][n]);
            }
#pragma unroll
            for (int mt = 0; mt < 4; mt++)
#pragma unroll
                for (int nt = 0; nt < 4; nt++)
                    mma8(acc[mt][nt], a[mt], b[nt]);
        }
        __syncthreads();
    }

    // ---- epilogue ----
    // acc[mt][nt]: c0=(grp,2tg) c1=(grp,2tg+1) c2=(grp+8,2tg) c3=(grp+8,2tg+1)
#pragma unroll
    for (int nt = 0; nt < 4; nt++) {
        int cc = col0 + warp_n * 32 + nt * 8 + 2 * tg;   // even
        float b0 = 0.f, b1 = 0.f;
        if (cc < D0) { b0 = bias[cc]; b1 = bias[cc + 1]; }
#pragma unroll
        for (int mt = 0; mt < 4; mt++) {
            int r0 = row0 + warp_m * 64 + mt * 16 + grp;
            int r1 = r0 + 8;
#pragma unroll
            for (int h = 0; h < 2; h++) {
                int r = h ? r1 : r0;
                if (r >= M) continue;
                float v0 = acc[mt][nt][h * 2 + 0] + b0;
                float v1 = acc[mt][nt][h * 2 + 1] + b1;
                if (EPI == 1) { v0 = fmaxf(v0, 0.f); v1 = fmaxf(v1, 0.f); }
                if (EPI == 2) {
                    if (cc < D0) {
                        int zi = zidx[r];
                        v0 += emb[(size_t)zi * D0 + cc];
                        v1 += emb[(size_t)zi * D0 + cc + 1];
                    }
                }
                if (EPI == 4) {
                    if (cc < D0) {
                        float2 o = make_float2(v0, v1);
                        *(float2*)(C + (size_t)r * D0 + cc) = o;
                    }
                } else {
                    if (cc < DP) {
                        float2 o = make_float2(v0, v1);
                        *(float2*)(C + (size_t)r * DP + cc) = o;
                    }
                }
            }
        }
    }
}

static void gemm_launch(int epi, const float* A, const float* A2, const float* rs,
                        const float* W, const float* bias, float* C, int M,
                        const int* z, const float* emb) {
    dim3 grid(3, (M + BM - 1) / BM);
    switch (epi) {
        case 0: k_gemm<0><<<grid, 256>>>(A, A2, rs, W, bias, C, M, z, emb); break;
        case 1: k_gemm<1><<<grid, 256>>>(A, A2, rs, W, bias, C, M, z, emb); break;
        case 2: k_gemm<2><<<grid, 256>>>(A, A2, rs, W, bias, C, M, z, emb); break;
        case 4: k_gemm<4><<<grid, 256>>>(A, A2, rs, W, bias, C, M, z, emb); break;
    }
}

// ---------------------------------------------------------------------------
extern "C" void kernel_launch(void* const* d_in, const int* in_sizes, int n_in,
                              void* d_out, int out_size) {
    const int*   z     = (const int*)d_in[0];
    const float* ch    = (const float*)d_in[1];
    const float* fc    = (const float*)d_in[2];
    const int*   ei    = (const int*)d_in[3];
    const float* ea    = (const float*)d_in[4];
    const int*   batch = (const int*)d_in[5];

    int o = (in_sizes[6] == 1) ? 7 : 6;  // skip num_graphs scalar if present
    const float* atom_emb = (const float*)d_in[o + 0];
    const float* nW1   = (const float*)d_in[o + 1];
    const float* nb1   = (const float*)d_in[o + 2];
    const float* nW2   = (const float*)d_in[o + 3];
    const float* nb2   = (const float*)d_in[o + 4];
    const float* eW1   = (const float*)d_in[o + 5];
    const float* eb1   = (const float*)d_in[o + 6];
    const float* eW2   = (const float*)d_in[o + 7];
    const float* eb2   = (const float*)d_in[o + 8];
    const float* mW1   = (const float*)d_in[o + 9];
    const float* mb1   = (const float*)d_in[o + 10];
    const float* mW2   = (const float*)d_in[o + 11];
    const float* mb2   = (const float*)d_in[o + 12];
    const float* gamma = (const float*)d_in[o + 13];
    const float* beta  = (const float*)d_in[o + 14];
    const float* pW    = (const float*)d_in[o + 15];
    const float* pb    = (const float*)d_in[o + 16];

    int N = in_sizes[0];
    int E = in_sizes[3] / 2;
    int G = out_size / D0;
    const int* src = ei;
    const int* dst = ei + E;

    float *ph, *pagg, *pt, *pe, *ptmp, *ppool, *pcnt, *pinv;
    cudaGetSymbolAddress((void**)&ph,    g_h);
    cudaGetSymbolAddress((void**)&pagg,  g_agg);
    cudaGetSymbolAddress((void**)&pt,    g_t);
    cudaGetSymbolAddress((void**)&pe,    g_e);
    cudaGetSymbolAddress((void**)&ptmp,  g_tmp);
    cudaGetSymbolAddress((void**)&ppool, g_pool);
    cudaGetSymbolAddress((void**)&pcnt,  g_cnt);
    cudaGetSymbolAddress((void**)&pinv,  g_inv);

    int n4 = N * 80;

    // node encoder: h = atom_emb[z] + relu(attr@nW1+nb1)@nW2 + nb2
    k_node_hidden<<<(n4 + 255) / 256, 256>>>(ch, fc, nW1, nb1, pt, N);
    gemm_launch(2, pt, nullptr, nullptr, nW2, nb2, ph, N, z, atom_emb);

    // edge encoder: e = relu(edge_attr@eW1+eb1)@eW2 + eb2
    int e4 = E * 80;
    k_edge_hidden<<<(e4 + 255) / 256, 256>>>(ea, eW1, eb1, ptmp, E);
    gemm_launch(0, ptmp, nullptr, nullptr, eW2, eb2, pe, E, nullptr, nullptr);

    for (int l = 0; l < NLAYER; l++) {
        k_fill0<<<(n4 + 255) / 256, 256>>>((float4*)pagg, n4);
        k_scatter<<<(E * 32 + 255) / 256, 256>>>(src, dst, E);
        // t = relu((h + agg) @ mW1[l] + mb1[l])
        gemm_launch(1, ph, pagg, nullptr, mW1 + (size_t)l * D0 * D0, mb1 + (size_t)l * D0,
                    pt, N, nullptr, nullptr);
        // agg = t @ mW2[l] + mb2[l]
        gemm_launch(0, pt, nullptr, nullptr, mW2 + (size_t)l * D0 * D0, mb2 + (size_t)l * D0,
                    pagg, N, nullptr, nullptr);
        // BN stats + apply
        k_zerostats<<<1, DP>>>();
        k_stats<<<(N + 511) / 512, DP>>>(pagg, N);
        k_bnprep<<<1, DP>>>(gamma + (size_t)l * D0, beta + (size_t)l * D0, 1.f / (float)N);
        k_bnapply<<<(n4 + 255) / 256, 256>>>(N);
    }

    // mean pooling + projection
    int g4 = G * 80;
    k_fill0<<<(g4 + 255) / 256, 256>>>((float4*)ppool, g4);
    k_fill0<<<(G / 4 + 255) / 256, 256>>>((float4*)pcnt, G / 4);
    k_count<<<(N + 255) / 256, 256>>>(batch, N);
    k_pool<<<(N * 32 + 255) / 256, 256>>>(batch, N);
    k_inv<<<(G + 255) / 256, 256>>>(G);
    gemm_launch(4, ppool, nullptr, pinv, pW, pb, (float*)d_out, G, nullptr, nullptr);
}

// round 3
// speedup vs baseline: 2.6100x; 1.1373x over previous
#include <cuda_runtime.h>
#include <cstdint>

// ---------------------------------------------------------------------------
// GINE encoder. GEMMs: tf32 mma.sync + double-buffered cp.async pipeline.
// Feature dim padded 300 -> 320 (pad cols identically 0 everywhere).
// ---------------------------------------------------------------------------

#define D0      300
#define DP      320
#define NMAX    100000
#define EMAX    250000
#define GMAX    4096
#define NLAYER  5
#define BN_EPS  1e-5f

__device__ float g_h  [(size_t)NMAX * DP];
__device__ float g_agg[(size_t)NMAX * DP];
__device__ float g_t  [(size_t)NMAX * DP];
__device__ float g_e  [(size_t)EMAX * DP];
__device__ float g_tmp[(size_t)EMAX * DP];
__device__ float g_pool[(size_t)GMAX * DP];
__device__ float g_cnt[GMAX];
__device__ float g_sum[DP];
__device__ float g_sq [DP];
__device__ float g_scale[DP];
__device__ float g_shift[DP];

// ---------------------------------------------------------------------------
__global__ void k_fill0(float4* p, int n4) {
    int i = blockIdx.x * blockDim.x + threadIdx.x;
    if (i < n4) p[i] = make_float4(0.f, 0.f, 0.f, 0.f);
}

__global__ void k_zerostats() {
    int j = threadIdx.x;
    g_sum[j] = 0.f;
    g_sq[j]  = 0.f;
}

__global__ void k_node_hidden(const float* __restrict__ ch, const float* __restrict__ fc,
                              const float* __restrict__ W,  const float* __restrict__ b,
                              float* __restrict__ out, int N) {
    int idx = blockIdx.x * blockDim.x + threadIdx.x;
    if (idx >= N * 80) return;
    int i = idx / 80;
    int c = (idx - i * 80) * 4;
    float a0 = ch[i], a1 = fc[i];
    float4 o;
    float* op = &o.x;
#pragma unroll
    for (int j = 0; j < 4; j++) {
        int col = c + j;
        float v = 0.f;
        if (col < D0)
            v = fmaxf(fmaf(a0, W[col], fmaf(a1, W[D0 + col], b[col])), 0.f);
        op[j] = v;
    }
    *(float4*)(out + (size_t)i * DP + c) = o;
}

__global__ void k_edge_hidden(const float* __restrict__ ea,
                              const float* __restrict__ W, const float* __restrict__ b,
                              float* __restrict__ out, int E) {
    int idx = blockIdx.x * blockDim.x + threadIdx.x;
    if (idx >= E * 80) return;
    int i = idx / 80;
    int c = (idx - i * 80) * 4;
    float a0 = ea[(size_t)i * 3 + 0];
    float a1 = ea[(size_t)i * 3 + 1];
    float a2 = ea[(size_t)i * 3 + 2];
    float4 o;
    float* op = &o.x;
#pragma unroll
    for (int j = 0; j < 4; j++) {
        int col = c + j;
        float v = 0.f;
        if (col < D0)
            v = fmaxf(fmaf(a0, W[col], fmaf(a1, W[D0 + col], fmaf(a2, W[2 * D0 + col], b[col]))), 0.f);
        op[j] = v;
    }
    *(float4*)(out + (size_t)i * DP + c) = o;
}

// one warp per edge: agg[dst] += relu(h[src] + e[edge]); agg pre-seeded with h
__global__ void k_scatter(const int* __restrict__ src, const int* __restrict__ dst, int E) {
    int w = (blockIdx.x * blockDim.x + threadIdx.x) >> 5;
    int lane = threadIdx.x & 31;
    if (w >= E) return;
    int s = src[w], d = dst[w];
    const float4* hp = (const float4*)(g_h + (size_t)s * DP);
    const float4* ep = (const float4*)(g_e + (size_t)w * DP);
    float* ap = g_agg + (size_t)d * DP;
#pragma unroll
    for (int it = 0; it < 3; it++) {
        int c = lane + it * 32;
        if (c < 75) {
            float4 hv = hp[c], ev = ep[c];
            float x = fmaxf(hv.x + ev.x, 0.f);
            float y = fmaxf(hv.y + ev.y, 0.f);
            float z = fmaxf(hv.z + ev.z, 0.f);
            float v = fmaxf(hv.w + ev.w, 0.f);
            asm volatile("red.global.add.v4.f32 [%0], {%1,%2,%3,%4};"
                         :: "l"(ap + 4 * c), "f"(x), "f"(y), "f"(z), "f"(v) : "memory");
        }
    }
}

__global__ void k_bnprep(const float* __restrict__ gamma, const float* __restrict__ beta, float invN) {
    int j = threadIdx.x;
    float mu  = g_sum[j] * invN;
    float var = g_sq[j] * invN - mu * mu;
    float inv = rsqrtf(var + BN_EPS);
    float ga = (j < D0) ? gamma[j] : 0.f;
    float be = (j < D0) ? beta[j]  : 0.f;
    float sc = ga * inv;
    g_scale[j] = sc;
    g_shift[j] = be - mu * sc;
}

// h = relu(agg*scale+shift); also seed agg = h for next layer
__global__ void k_bnapply(int N) {
    int idx = blockIdx.x * blockDim.x + threadIdx.x;
    if (idx >= N * 80) return;
    int i = idx / 80;
    int c = (idx - i * 80) * 4;
    size_t off = (size_t)i * DP + c;
    float4 v = *(const float4*)(g_agg + off);
    v.x = fmaxf(fmaf(v.x, g_scale[c + 0], g_shift[c + 0]), 0.f);
    v.y = fmaxf(fmaf(v.y, g_scale[c + 1], g_shift[c + 1]), 0.f);
    v.z = fmaxf(fmaf(v.z, g_scale[c + 2], g_shift[c + 2]), 0.f);
    v.w = fmaxf(fmaf(v.w, g_scale[c + 3], g_shift[c + 3]), 0.f);
    *(float4*)(g_h + off) = v;
    *(float4*)(g_agg + off) = v;
}

__global__ void k_count(const int* __restrict__ batch, int N) {
    int i = blockIdx.x * blockDim.x + threadIdx.x;
    if (i < N) atomicAdd(&g_cnt[batch[i]], 1.f);
}

__global__ void k_pool(const int* __restrict__ batch, int N) {
    int w = (blockIdx.x * blockDim.x + threadIdx.x) >> 5;
    int lane = threadIdx.x & 31;
    if (w >= N) return;
    int g = batch[w];
    const float4* hp = (const float4*)(g_h + (size_t)w * DP);
    float* pp = g_pool + (size_t)g * DP;
#pragma unroll
    for (int it = 0; it < 3; it++) {
        int c = lane + it * 32;
        if (c < 75) {
            float4 v = hp[c];
            asm volatile("red.global.add.v4.f32 [%0], {%1,%2,%3,%4};"
                         :: "l"(pp + 4 * c), "f"(v.x), "f"(v.y), "f"(v.z), "f"(v.w) : "memory");
        }
    }
}

// scale pooled rows by 1/count
__global__ void k_scalepool(int G) {
    int idx = blockIdx.x * blockDim.x + threadIdx.x;
    if (idx >= G * 80) return;
    int i = idx / 80;
    int c = (idx - i * 80) * 4;
    float s = 1.f / fmaxf(g_cnt[i], 1.f);
    float4 v = *(const float4*)(g_pool + (size_t)i * DP + c);
    v.x *= s; v.y *= s; v.z *= s; v.w *= s;
    *(float4*)(g_pool + (size_t)i * DP + c) = v;
}

// ---------------------------------------------------------------------------
// Tensor-core GEMM with 2-stage cp.async pipeline.
// C[M,*] = epi( A[M,DP] @ W[300,300] + bias )
// Block 128x128, BK=32, 8 warps (2M x 4N), warp tile 64x32.
// EPI: 0 plain, 1 relu, 2 emb gather + dual write (C,Cb), 3 BN stats,
//      4 stride-300 output.
// ---------------------------------------------------------------------------
#define BM 128
#define BN 128
#define BK 32
#define ASTR 36
#define BSTR 132
#define ASZ  (BM * ASTR)            // 4608 floats
#define BSZ  (BK * BSTR)            // 4224 floats
#define STG  (ASZ + BSZ)            // 8832 floats per stage
#define SMEM_BYTES (2 * STG * 4)    // 70656 B

__device__ __forceinline__ uint32_t tf32b(float x) {
    uint32_t y;
    asm("cvt.rna.tf32.f32 %0, %1;" : "=r"(y) : "f"(x));
    return y;
}

__device__ __forceinline__ void cp16(uint32_t dst, const float* src, bool pred) {
    int sz = pred ? 16 : 0;
    asm volatile("cp.async.ca.shared.global [%0], [%1], 16, %2;"
                 :: "r"(dst), "l"(src), "r"(sz));
}

__device__ __forceinline__ void mma8(float c[4], const uint32_t a[4], const uint32_t b[2]) {
    asm volatile(
        "mma.sync.aligned.m16n8k8.row.col.f32.tf32.tf32.f32 "
        "{%0,%1,%2,%3}, {%4,%5,%6,%7}, {%8,%9}, {%0,%1,%2,%3};"
        : "+f"(c[0]), "+f"(c[1]), "+f"(c[2]), "+f"(c[3])
        : "r"(a[0]), "r"(a[1]), "r"(a[2]), "r"(a[3]), "r"(b[0]), "r"(b[1]));
}

template <int EPI>
__global__ __launch_bounds__(256, 2)
void k_gemm(const float* __restrict__ A,
            const float* __restrict__ W, const float* __restrict__ bias,
            float* __restrict__ C, float* __restrict__ Cb, int M,
            const int* __restrict__ zidx, const float* __restrict__ emb) {
    extern __shared__ float sm[];

    const int tid = threadIdx.x;
    const int wid = tid >> 5;
    const int lane = tid & 31;
    const int warp_m = wid & 1;
    const int warp_n = wid >> 1;
    const int grp = lane >> 2;
    const int tg  = lane & 3;
    const int row0 = blockIdx.y * BM;
    const int col0 = blockIdx.x * BN;

    const int a_r  = tid >> 3;            // 0..31 base rows (x4 iters -> 128)
    const int a_c4 = (tid & 7) * 4;
    const int b_k  = tid >> 5;            // 0..7 (x4 iters -> 32)
    const int b_c4 = (tid & 31) * 4;

    uint32_t smbase = (uint32_t)__cvta_generic_to_shared(sm);

    float acc[4][4][4];
#pragma unroll
    for (int i = 0; i < 4; i++)
#pragma unroll
        for (int j = 0; j < 4; j++)
#pragma unroll
            for (int k = 0; k < 4; k++) acc[i][j][k] = 0.f;

    // tile loader
    auto load_stage = [&](int stage, int k0) {
        uint32_t as = smbase + (stage * STG) * 4;
        uint32_t bs = smbase + (stage * STG + ASZ) * 4;
#pragma unroll
        for (int it = 0; it < 4; it++) {
            int r = a_r + it * 32;
            int grow = row0 + r;
            bool ok = grow < M;
            const float* src = A + (size_t)(ok ? grow : 0) * DP + k0 + a_c4;
            cp16(as + (r * ASTR + a_c4) * 4, src, ok);
        }
#pragma unroll
        for (int it = 0; it < 4; it++) {
            int k = b_k + it * 8;
            int gk = k0 + k;
            int gc = col0 + b_c4;
            bool ok = (gk < D0) && (gc < D0);
            const float* src = W + (size_t)(ok ? gk : 0) * D0 + (ok ? gc : 0);
            cp16(bs + (k * BSTR + b_c4) * 4, src, ok);
        }
    };

    load_stage(0, 0);
    asm volatile("cp.async.commit_group;");

    const int NK = DP / BK;  // 10
    for (int it = 0; it < NK; it++) {
        int nxt = it + 1;
        if (nxt < NK) {
            load_stage(nxt & 1, nxt * BK);
            asm volatile("cp.async.commit_group;");
            asm volatile("cp.async.wait_group 1;");
        } else {
            asm volatile("cp.async.wait_group 0;");
        }
        __syncthreads();

        const float* As_ = sm + (it & 1) * STG;
        const float* Bs_ = As_ + ASZ;
#pragma unroll
        for (int ks = 0; ks < 4; ks++) {
            const int kk = ks * 8;
            uint32_t a[4][4], b[4][2];
#pragma unroll
            for (int mt = 0; mt < 4; mt++) {
                int m = warp_m * 64 + mt * 16 + grp;
                a[mt][0] = tf32b(As_[m * ASTR + kk + tg]);
                a[mt][1] = tf32b(As_[(m + 8) * ASTR + kk + tg]);
                a[mt][2] = tf32b(As_[m * ASTR + kk + tg + 4]);
                a[mt][3] = tf32b(As_[(m + 8) * ASTR + kk + tg + 4]);
            }
#pragma unroll
            for (int nt = 0; nt < 4; nt++) {
                int n = warp_n * 32 + nt * 8 + grp;
                b[nt][0] = tf32b(Bs_[(kk + tg) * BSTR + n]);
                b[nt][1] = tf32b(Bs_[(kk + tg + 4) * BSTR + n]);
            }
#pragma unroll
            for (int mt = 0; mt < 4; mt++)
#pragma unroll
                for (int nt = 0; nt < 4; nt++)
                    mma8(acc[mt][nt], a[mt], b[nt]);
        }
        __syncthreads();
    }

    // ---- epilogue ----
    float lsum[4][2], lsq[4][2];
    if (EPI == 3) {
#pragma unroll
        for (int nt = 0; nt < 4; nt++) { lsum[nt][0] = lsum[nt][1] = 0.f; lsq[nt][0] = lsq[nt][1] = 0.f; }
    }

#pragma unroll
    for (int nt = 0; nt < 4; nt++) {
        int cc = col0 + warp_n * 32 + nt * 8 + 2 * tg;
        float b0 = 0.f, b1 = 0.f;
        if (cc < D0) { b0 = bias[cc]; b1 = bias[cc + 1]; }
#pragma unroll
        for (int mt = 0; mt < 4; mt++) {
            int rbase = row0 + warp_m * 64 + mt * 16 + grp;
#pragma unroll
            for (int h = 0; h < 2; h++) {
                int r = rbase + h * 8;
                if (r >= M) continue;
                float v0 = acc[mt][nt][h * 2 + 0] + b0;
                float v1 = acc[mt][nt][h * 2 + 1] + b1;
                if (EPI == 1) { v0 = fmaxf(v0, 0.f); v1 = fmaxf(v1, 0.f); }
                if (EPI == 2) {
                    if (cc < D0) {
                        int zi = zidx[r];
                        v0 += emb[(size_t)zi * D0 + cc];
                        v1 += emb[(size_t)zi * D0 + cc + 1];
                    }
                }
                if (EPI == 3) {
                    lsum[nt][0] += v0; lsum[nt][1] += v1;
                    lsq[nt][0] += v0 * v0; lsq[nt][1] += v1 * v1;
                }
                if (EPI == 4) {
                    if (cc < D0)
                        *(float2*)(C + (size_t)r * D0 + cc) = make_float2(v0, v1);
                } else {
                    if (cc < DP) {
                        *(float2*)(C + (size_t)r * DP + cc) = make_float2(v0, v1);
                        if (EPI == 2)
                            *(float2*)(Cb + (size_t)r * DP + cc) = make_float2(v0, v1);
                    }
                }
            }
        }
    }

    if (EPI == 3) {
        __syncthreads();
        float* ssum = sm;        // 128
        float* ssq  = sm + 128;  // 128
        if (tid < 128) { ssum[tid] = 0.f; ssq[tid] = 0.f; }
        __syncthreads();
#pragma unroll
        for (int nt = 0; nt < 4; nt++) {
            int lc = warp_n * 32 + nt * 8 + 2 * tg;
            atomicAdd(&ssum[lc], lsum[nt][0]);
            atomicAdd(&ssum[lc + 1], lsum[nt][1]);
            atomicAdd(&ssq[lc], lsq[nt][0]);
            atomicAdd(&ssq[lc + 1], lsq[nt][1]);
        }
        __syncthreads();
        if (tid < 128) {
            int c = col0 + tid;
            if (c < DP) {
                atomicAdd(&g_sum[c], ssum[tid]);
                atomicAdd(&g_sq[c], ssq[tid]);
            }
        }
    }
}

static void gemm_launch(int epi, const float* A, const float* W, const float* bias,
                        float* C, float* Cb, int M, const int* z, const float* emb) {
    dim3 grid(3, (M + BM - 1) / BM);
    switch (epi) {
        case 0: k_gemm<0><<<grid, 256, SMEM_BYTES>>>(A, W, bias, C, Cb, M, z, emb); break;
        case 1: k_gemm<1><<<grid, 256, SMEM_BYTES>>>(A, W, bias, C, Cb, M, z, emb); break;
        case 2: k_gemm<2><<<grid, 256, SMEM_BYTES>>>(A, W, bias, C, Cb, M, z, emb); break;
        case 3: k_gemm<3><<<grid, 256, SMEM_BYTES>>>(A, W, bias, C, Cb, M, z, emb); break;
        case 4: k_gemm<4><<<grid, 256, SMEM_BYTES>>>(A, W, bias, C, Cb, M, z, emb); break;
    }
}

// ---------------------------------------------------------------------------
extern "C" void kernel_launch(void* const* d_in, const int* in_sizes, int n_in,
                              void* d_out, int out_size) {
    static bool attr_done = false;
    if (!attr_done) {
        cudaFuncSetAttribute(k_gemm<0>, cudaFuncAttributeMaxDynamicSharedMemorySize, SMEM_BYTES);
        cudaFuncSetAttribute(k_gemm<1>, cudaFuncAttributeMaxDynamicSharedMemorySize, SMEM_BYTES);
        cudaFuncSetAttribute(k_gemm<2>, cudaFuncAttributeMaxDynamicSharedMemorySize, SMEM_BYTES);
        cudaFuncSetAttribute(k_gemm<3>, cudaFuncAttributeMaxDynamicSharedMemorySize, SMEM_BYTES);
        cudaFuncSetAttribute(k_gemm<4>, cudaFuncAttributeMaxDynamicSharedMemorySize, SMEM_BYTES);
        attr_done = true;
    }

    const int*   z     = (const int*)d_in[0];
    const float* ch    = (const float*)d_in[1];
    const float* fc    = (const float*)d_in[2];
    const int*   ei    = (const int*)d_in[3];
    const float* ea    = (const float*)d_in[4];
    const int*   batch = (const int*)d_in[5];

    int o = (in_sizes[6] == 1) ? 7 : 6;
    const float* atom_emb = (const float*)d_in[o + 0];
    const float* nW1   = (const float*)d_in[o + 1];
    const float* nb1   = (const float*)d_in[o + 2];
    const float* nW2   = (const float*)d_in[o + 3];
    const float* nb2   = (const float*)d_in[o + 4];
    const float* eW1   = (const float*)d_in[o + 5];
    const float* eb1   = (const float*)d_in[o + 6];
    const float* eW2   = (const float*)d_in[o + 7];
    const float* eb2   = (const float*)d_in[o + 8];
    const float* mW1   = (const float*)d_in[o + 9];
    const float* mb1   = (const float*)d_in[o + 10];
    const float* mW2   = (const float*)d_in[o + 11];
    const float* mb2   = (const float*)d_in[o + 12];
    const float* gamma = (const float*)d_in[o + 13];
    const float* beta  = (const float*)d_in[o + 14];
    const float* pW    = (const float*)d_in[o + 15];
    const float* pb    = (const float*)d_in[o + 16];

    int N = in_sizes[0];
    int E = in_sizes[3] / 2;
    int G = out_size / D0;
    const int* src = ei;
    const int* dst = ei + E;

    float *ph, *pagg, *pt, *pe, *ptmp, *ppool, *pcnt;
    cudaGetSymbolAddress((void**)&ph,    g_h);
    cudaGetSymbolAddress((void**)&pagg,  g_agg);
    cudaGetSymbolAddress((void**)&pt,    g_t);
    cudaGetSymbolAddress((void**)&pe,    g_e);
    cudaGetSymbolAddress((void**)&ptmp,  g_tmp);
    cudaGetSymbolAddress((void**)&ppool, g_pool);
    cudaGetSymbolAddress((void**)&pcnt,  g_cnt);

    int n4 = N * 80;

    // node encoder: h = atom_emb[z] + relu(attr@nW1+nb1)@nW2 + nb2; agg seeded = h
    k_node_hidden<<<(n4 + 255) / 256, 256>>>(ch, fc, nW1, nb1, pt, N);
    gemm_launch(2, pt, nW2, nb2, ph, pagg, N, z, atom_emb);

    // edge encoder: e = relu(edge_attr@eW1+eb1)@eW2 + eb2
    int e4 = E * 80;
    k_edge_hidden<<<(e4 + 255) / 256, 256>>>(ea, eW1, eb1, ptmp, E);
    gemm_launch(0, ptmp, eW2, eb2, pe, nullptr, E, nullptr, nullptr);

    for (int l = 0; l < NLAYER; l++) {
        // agg (= h) += sum relu(h[src]+e)
        k_scatter<<<(E * 32 + 255) / 256, 256>>>(src, dst, E);
        // t = relu(agg @ mW1 + mb1)
        gemm_launch(1, pagg, mW1 + (size_t)l * D0 * D0, mb1 + (size_t)l * D0,
                    pt, nullptr, N, nullptr, nullptr);
        // agg = t @ mW2 + mb2, with fused column stats
        k_zerostats<<<1, DP>>>();
        gemm_launch(3, pt, mW2 + (size_t)l * D0 * D0, mb2 + (size_t)l * D0,
                    pagg, nullptr, N, nullptr, nullptr);
        k_bnprep<<<1, DP>>>(gamma + (size_t)l * D0, beta + (size_t)l * D0, 1.f / (float)N);
        k_bnapply<<<(n4 + 255) / 256, 256>>>(N);  // h = relu(bn(agg)); agg = h
    }

    // mean pooling + projection
    int g4 = G * 80;
    k_fill0<<<(g4 + 255) / 256, 256>>>((float4*)ppool, g4);
    k_fill0<<<(G / 4 + 255) / 256, 256>>>((float4*)pcnt, G / 4);
    k_count<<<(N + 255) / 256, 256>>>(batch, N);
    k_pool<<<(N * 32 + 255) / 256, 256>>>(batch, N);
    k_scalepool<<<(g4 + 255) / 256, 256>>>(G);
    gemm_launch(4, ppool, pW, pb, (float*)d_out, nullptr, G, nullptr, nullptr);
}

// round 4
// speedup vs baseline: 3.1956x; 1.2244x over previous
#include <cuda_runtime.h>
#include <cuda_fp16.h>
#include <cstdint>

// ---------------------------------------------------------------------------
// GINE encoder. GEMMs: fp16 mma.m16n8k16 + ldmatrix + cp.async double buffer.
// Feature dim padded 300 -> 320 (pad cols identically 0 everywhere).
// Activations stored fp16 (same 10-bit mantissa as tf32 -> same accuracy),
// graph accumulation (scatter/pool/BN stats) kept in fp32.
// ---------------------------------------------------------------------------

#define D0      300
#define DP      320
#define NMAX    100000
#define EMAX    250000
#define GMAX    4096
#define NLAYER  5
#define BN_EPS  1e-5f

__device__ __half g_h16[(size_t)NMAX * DP];
__device__ __half g_t16[(size_t)NMAX * DP];
__device__ __half g_a16[(size_t)NMAX * DP];
__device__ __half g_e16[(size_t)EMAX * DP];
__device__ __half g_x16[(size_t)EMAX * DP];
__device__ __half g_p16[(size_t)GMAX * DP];
__device__ __half g_w16[13 * DP * DP];        // 13 transposed+padded weight mats
__device__ float  g_agg[(size_t)NMAX * DP];
__device__ float  g_pool[(size_t)GMAX * DP];
__device__ float  g_cnt[GMAX];
__device__ float  g_sum[DP];
__device__ float  g_sq [DP];
__device__ float  g_scale[DP];
__device__ float  g_shift[DP];

// ---------------------------------------------------------------------------
__device__ __forceinline__ uint2 pack4h(float a, float b, float c, float d) {
    __half2 h0 = __floats2half2_rn(a, b);
    __half2 h1 = __floats2half2_rn(c, d);
    uint2 u;
    u.x = *reinterpret_cast<uint32_t*>(&h0);
    u.y = *reinterpret_cast<uint32_t*>(&h1);
    return u;
}

__global__ void k_fill0(float4* p, int n4) {
    int i = blockIdx.x * blockDim.x + threadIdx.x;
    if (i < n4) p[i] = make_float4(0.f, 0.f, 0.f, 0.f);
}

__global__ void k_zerostats() {
    int j = threadIdx.x;
    g_sum[j] = 0.f;
    g_sq[j]  = 0.f;
}

// W[300,300] -> Wt fp16 [320 n][320 k], zero padded
__global__ void k_wcvt(const float* __restrict__ W, __half* __restrict__ out) {
    int idx = blockIdx.x * blockDim.x + threadIdx.x;
    if (idx >= DP * DP) return;
    int k = idx / DP, n = idx % DP;
    float v = (k < D0 && n < D0) ? W[k * D0 + n] : 0.f;
    out[(size_t)n * DP + k] = __float2half_rn(v);
}

__global__ void k_node_hidden(const float* __restrict__ ch, const float* __restrict__ fc,
                              const float* __restrict__ W,  const float* __restrict__ b,
                              __half* __restrict__ out, int N) {
    int idx = blockIdx.x * blockDim.x + threadIdx.x;
    if (idx >= N * 80) return;
    int i = idx / 80;
    int c = (idx - i * 80) * 4;
    float a0 = ch[i], a1 = fc[i];
    float o[4];
#pragma unroll
    for (int j = 0; j < 4; j++) {
        int col = c + j;
        o[j] = (col < D0)
             ? fmaxf(fmaf(a0, W[col], fmaf(a1, W[D0 + col], b[col])), 0.f) : 0.f;
    }
    *(uint2*)(out + (size_t)i * DP + c) = pack4h(o[0], o[1], o[2], o[3]);
}

__global__ void k_edge_hidden(const float* __restrict__ ea,
                              const float* __restrict__ W, const float* __restrict__ b,
                              __half* __restrict__ out, int E) {
    int idx = blockIdx.x * blockDim.x + threadIdx.x;
    if (idx >= E * 80) return;
    int i = idx / 80;
    int c = (idx - i * 80) * 4;
    float a0 = ea[(size_t)i * 3 + 0];
    float a1 = ea[(size_t)i * 3 + 1];
    float a2 = ea[(size_t)i * 3 + 2];
    float o[4];
#pragma unroll
    for (int j = 0; j < 4; j++) {
        int col = c + j;
        o[j] = (col < D0)
             ? fmaxf(fmaf(a0, W[col], fmaf(a1, W[D0 + col], fmaf(a2, W[2 * D0 + col], b[col]))), 0.f) : 0.f;
    }
    *(uint2*)(out + (size_t)i * DP + c) = pack4h(o[0], o[1], o[2], o[3]);
}

// one warp per edge: agg[dst] += relu(h[src] + e[edge]); agg pre-seeded with h
__global__ void k_scatter(const int* __restrict__ src, const int* __restrict__ dst, int E) {
    int w = (blockIdx.x * blockDim.x + threadIdx.x) >> 5;
    int lane = threadIdx.x & 31;
    if (w >= E) return;
    int s = src[w], d = dst[w];
    const uint4* hp = (const uint4*)(g_h16 + (size_t)s * DP);
    const uint4* ep = (const uint4*)(g_e16 + (size_t)w * DP);
    float* ap = g_agg + (size_t)d * DP;
#pragma unroll
    for (int it = 0; it < 2; it++) {
        int c = lane + it * 32;
        if (c < 38) {  // cols 304..319 identically zero
            uint4 hu = hp[c], eu = ep[c];
            const __half2* h2 = (const __half2*)&hu;
            const __half2* e2 = (const __half2*)&eu;
            float v[8];
#pragma unroll
            for (int j = 0; j < 4; j++) {
                float2 fh = __half22float2(h2[j]);
                float2 fe = __half22float2(e2[j]);
                v[2 * j]     = fmaxf(fh.x + fe.x, 0.f);
                v[2 * j + 1] = fmaxf(fh.y + fe.y, 0.f);
            }
            asm volatile("red.global.add.v4.f32 [%0], {%1,%2,%3,%4};"
                         :: "l"(ap + 8 * c), "f"(v[0]), "f"(v[1]), "f"(v[2]), "f"(v[3]) : "memory");
            asm volatile("red.global.add.v4.f32 [%0], {%1,%2,%3,%4};"
                         :: "l"(ap + 8 * c + 4), "f"(v[4]), "f"(v[5]), "f"(v[6]), "f"(v[7]) : "memory");
        }
    }
}

// agg fp32 -> a16 fp16
__global__ void k_cvt(int N) {
    int idx = blockIdx.x * blockDim.x + threadIdx.x;
    if (idx >= N * 80) return;
    float4 v = *(const float4*)(g_agg + (size_t)idx * 4);
    *(uint2*)(g_a16 + (size_t)idx * 4) = pack4h(v.x, v.y, v.z, v.w);
}

__global__ void k_bnprep(const float* __restrict__ gamma, const float* __restrict__ beta, float invN) {
    int j = threadIdx.x;
    float mu  = g_sum[j] * invN;
    float var = g_sq[j] * invN - mu * mu;
    float inv = rsqrtf(var + BN_EPS);
    float ga = (j < D0) ? gamma[j] : 0.f;
    float be = (j < D0) ? beta[j]  : 0.f;
    float sc = ga * inv;
    g_scale[j] = sc;
    g_shift[j] = be - mu * sc;
}

// h16 = relu(bn(agg)); agg seeded = h (fp32)
__global__ void k_bnapply(int N) {
    int idx = blockIdx.x * blockDim.x + threadIdx.x;
    if (idx >= N * 80) return;
    int i = idx / 80;
    int c = (idx - i * 80) * 4;
    size_t off = (size_t)i * DP + c;
    float4 v = *(const float4*)(g_agg + off);
    v.x = fmaxf(fmaf(v.x, g_scale[c + 0], g_shift[c + 0]), 0.f);
    v.y = fmaxf(fmaf(v.y, g_scale[c + 1], g_shift[c + 1]), 0.f);
    v.z = fmaxf(fmaf(v.z, g_scale[c + 2], g_shift[c + 2]), 0.f);
    v.w = fmaxf(fmaf(v.w, g_scale[c + 3], g_shift[c + 3]), 0.f);
    *(uint2*)(g_h16 + off) = pack4h(v.x, v.y, v.z, v.w);
    *(float4*)(g_agg + off) = v;
}

__global__ void k_count(const int* __restrict__ batch, int N) {
    int i = blockIdx.x * blockDim.x + threadIdx.x;
    if (i < N) atomicAdd(&g_cnt[batch[i]], 1.f);
}

__global__ void k_pool(const int* __restrict__ batch, int N) {
    int w = (blockIdx.x * blockDim.x + threadIdx.x) >> 5;
    int lane = threadIdx.x & 31;
    if (w >= N) return;
    int g = batch[w];
    const uint4* hp = (const uint4*)(g_h16 + (size_t)w * DP);
    float* pp = g_pool + (size_t)g * DP;
#pragma unroll
    for (int it = 0; it < 2; it++) {
        int c = lane + it * 32;
        if (c < 38) {
            uint4 hu = hp[c];
            const __half2* h2 = (const __half2*)&hu;
            float v[8];
#pragma unroll
            for (int j = 0; j < 4; j++) {
                float2 f = __half22float2(h2[j]);
                v[2 * j] = f.x; v[2 * j + 1] = f.y;
            }
            asm volatile("red.global.add.v4.f32 [%0], {%1,%2,%3,%4};"
                         :: "l"(pp + 8 * c), "f"(v[0]), "f"(v[1]), "f"(v[2]), "f"(v[3]) : "memory");
            asm volatile("red.global.add.v4.f32 [%0], {%1,%2,%3,%4};"
                         :: "l"(pp + 8 * c + 4), "f"(v[4]), "f"(v[5]), "f"(v[6]), "f"(v[7]) : "memory");
        }
    }
}

__global__ void k_scalepool(int G) {
    int idx = blockIdx.x * blockDim.x + threadIdx.x;
    if (idx >= G * 80) return;
    int i = idx / 80;
    int c = (idx - i * 80) * 4;
    float s = 1.f / fmaxf(g_cnt[i], 1.f);
    float4 v = *(const float4*)(g_pool + (size_t)i * DP + c);
    *(uint2*)(g_p16 + (size_t)i * DP + c) = pack4h(v.x * s, v.y * s, v.z * s, v.w * s);
}

// ---------------------------------------------------------------------------
// fp16 tensor-core GEMM, 2-stage cp.async, ldmatrix fragments.
// C = epi( A[M,320]fp16 @ Wt^T + bias ),  Wt fp16 [320 n][320 k].
// Block 64x160, BK=32, 8 warps (2M x 4N), warp tile 32x40.
// SMEM rows: 40 halfs (80B) stride -> ldmatrix conflict-free.
// EPI: 0 half out, 1 relu half out, 2 +emb gather, dual write (half C, fp32 Cb),
//      3 fp32 out + BN col stats, 4 fp32 out stride 300.
// ---------------------------------------------------------------------------
#define BM 64
#define BN 160
#define BK 32
#define A_HALFS (BM * 40)                  // 2560
#define B_HALFS (BN * 40)                  // 6400
#define STG_HALFS (A_HALFS + B_HALFS)      // 8960
#define SMEM_BYTES (2 * STG_HALFS * 2)     // 35840

__device__ __forceinline__ void cp16(uint32_t dst, const void* src, bool pred) {
    int sz = pred ? 16 : 0;
    asm volatile("cp.async.ca.shared.global [%0], [%1], 16, %2;"
                 :: "r"(dst), "l"(src), "r"(sz));
}

__device__ __forceinline__ void ldsm4(uint32_t* r, uint32_t addr) {
    asm volatile("ldmatrix.sync.aligned.m8n8.x4.shared.b16 {%0,%1,%2,%3}, [%4];"
                 : "=r"(r[0]), "=r"(r[1]), "=r"(r[2]), "=r"(r[3]) : "r"(addr));
}
__device__ __forceinline__ void ldsm2(uint32_t* r, uint32_t addr) {
    asm volatile("ldmatrix.sync.aligned.m8n8.x2.shared.b16 {%0,%1}, [%2];"
                 : "=r"(r[0]), "=r"(r[1]) : "r"(addr));
}
__device__ __forceinline__ void mma16(float* c, const uint32_t* a, const uint32_t* b) {
    asm volatile("mma.sync.aligned.m16n8k16.row.col.f32.f16.f16.f32 "
                 "{%0,%1,%2,%3}, {%4,%5,%6,%7}, {%8,%9}, {%0,%1,%2,%3};"
                 : "+f"(c[0]), "+f"(c[1]), "+f"(c[2]), "+f"(c[3])
                 : "r"(a[0]), "r"(a[1]), "r"(a[2]), "r"(a[3]), "r"(b[0]), "r"(b[1]));
}

template <int EPI>
__global__ __launch_bounds__(256, 2)
void k_gemm(const __half* __restrict__ A, const __half* __restrict__ Wt,
            const float* __restrict__ bias, void* __restrict__ Cv,
            float* __restrict__ Cb, int M,
            const int* __restrict__ zidx, const float* __restrict__ emb) {
    extern __shared__ __align__(16) char smraw[];
    uint32_t smbase = (uint32_t)__cvta_generic_to_shared(smraw);

    const int tid = threadIdx.x;
    const int lane = tid & 31;
    const int wid = tid >> 5;
    const int warp_m = wid & 1;
    const int warp_n = wid >> 1;
    const int grp = lane >> 2;
    const int tg  = lane & 3;
    const int row0 = blockIdx.y * BM;
    const int col0 = blockIdx.x * BN;

    float acc[2][5][4];
#pragma unroll
    for (int i = 0; i < 2; i++)
#pragma unroll
        for (int j = 0; j < 5; j++)
#pragma unroll
            for (int k = 0; k < 4; k++) acc[i][j][k] = 0.f;

    const int a_r = tid >> 2, a_c = tid & 3;

    auto load_stage = [&](int stage, int k0) {
        uint32_t as = smbase + stage * (STG_HALFS * 2);
        uint32_t bs = as + A_HALFS * 2;
        {
            int grow = row0 + a_r;
            bool ok = grow < M;
            cp16(as + (a_r * 40 + a_c * 8) * 2,
                 A + (size_t)(ok ? grow : 0) * DP + k0 + a_c * 8, ok);
        }
#pragma unroll
        for (int it = 0; it < 3; it++) {
            int id = tid + it * 256;
            if (id < 640) {
                int r = id >> 2, c = id & 3;
                cp16(bs + (r * 40 + c * 8) * 2,
                     Wt + (size_t)(col0 + r) * DP + k0 + c * 8, true);
            }
        }
    };

    load_stage(0, 0);
    asm volatile("cp.async.commit_group;");

    const int NK = DP / BK;  // 10
    for (int it = 0; it < NK; it++) {
        if (it + 1 < NK) {
            load_stage((it + 1) & 1, (it + 1) * BK);
            asm volatile("cp.async.commit_group;");
            asm volatile("cp.async.wait_group 1;");
        } else {
            asm volatile("cp.async.wait_group 0;");
        }
        __syncthreads();

        uint32_t as = smbase + (it & 1) * (STG_HALFS * 2);
        uint32_t bs = as + A_HALFS * 2;
        const int jj = lane >> 3, rr = lane & 7;
#pragma unroll
        for (int ks = 0; ks < 2; ks++) {
            uint32_t a[2][4], b[5][2];
#pragma unroll
            for (int mt = 0; mt < 2; mt++) {
                int m = warp_m * 32 + mt * 16 + (jj & 1) * 8 + rr;
                int kh = ks * 16 + (jj >> 1) * 8;
                ldsm4(a[mt], as + (m * 40 + kh) * 2);
            }
#pragma unroll
            for (int p = 0; p < 2; p++) {
                int n = warp_n * 40 + p * 16 + (jj >> 1) * 8 + rr;
                int kh = ks * 16 + (jj & 1) * 8;
                uint32_t r4[4];
                ldsm4(r4, bs + (n * 40 + kh) * 2);
                b[2 * p][0] = r4[0]; b[2 * p][1] = r4[1];
                b[2 * p + 1][0] = r4[2]; b[2 * p + 1][1] = r4[3];
            }
            {
                int n = warp_n * 40 + 32 + rr;
                int kh = ks * 16 + (jj & 1) * 8;
                ldsm2(b[4], bs + (n * 40 + kh) * 2);
            }
#pragma unroll
            for (int mt = 0; mt < 2; mt++)
#pragma unroll
                for (int nt = 0; nt < 5; nt++)
                    mma16(acc[mt][nt], a[mt], b[nt]);
        }
        __syncthreads();
    }

    // ---- epilogue ----
    float lsum[5][2], lsq[5][2];
    if (EPI == 3) {
#pragma unroll
        for (int nt = 0; nt < 5; nt++) {
            lsum[nt][0] = lsum[nt][1] = 0.f;
            lsq[nt][0] = lsq[nt][1] = 0.f;
        }
    }

#pragma unroll
    for (int nt = 0; nt < 5; nt++) {
        int cc = col0 + warp_n * 40 + nt * 8 + 2 * tg;
        float b0 = 0.f, b1 = 0.f;
        if (cc < D0) { b0 = bias[cc]; b1 = bias[cc + 1]; }
#pragma unroll
        for (int mt = 0; mt < 2; mt++) {
#pragma unroll
            for (int h = 0; h < 2; h++) {
                int r = row0 + warp_m * 32 + mt * 16 + grp + h * 8;
                if (r >= M) continue;
                float v0 = acc[mt][nt][h * 2 + 0] + b0;
                float v1 = acc[mt][nt][h * 2 + 1] + b1;
                if (EPI == 1) { v0 = fmaxf(v0, 0.f); v1 = fmaxf(v1, 0.f); }
                if (EPI == 2) {
                    if (cc < D0) {
                        int zi = zidx[r];
                        v0 += emb[(size_t)zi * D0 + cc];
                        v1 += emb[(size_t)zi * D0 + cc + 1];
                    }
                }
                if (EPI == 3) {
                    lsum[nt][0] += v0; lsum[nt][1] += v1;
                    lsq[nt][0] += v0 * v0; lsq[nt][1] += v1 * v1;
                }
                if (EPI == 0 || EPI == 1 || EPI == 2) {
                    __half2 hv = __floats2half2_rn(v0, v1);
                    *(uint32_t*)((__half*)Cv + (size_t)r * DP + cc) =
                        *reinterpret_cast<uint32_t*>(&hv);
                    if (EPI == 2)
                        *(float2*)(Cb + (size_t)r * DP + cc) = make_float2(v0, v1);
                } else if (EPI == 3) {
                    *(float2*)((float*)Cv + (size_t)r * DP + cc) = make_float2(v0, v1);
                } else {  // EPI 4
                    if (cc < D0)
                        *(float2*)((float*)Cv + (size_t)r * D0 + cc) = make_float2(v0, v1);
                }
            }
        }
    }

    if (EPI == 3) {
        float* ssum = (float*)smraw;
        float* ssq  = ssum + BN;
        __syncthreads();
        if (tid < BN) { ssum[tid] = 0.f; ssq[tid] = 0.f; }
        __syncthreads();
#pragma unroll
        for (int nt = 0; nt < 5; nt++) {
            int lc = warp_n * 40 + nt * 8 + 2 * tg;
            atomicAdd(&ssum[lc],     lsum[nt][0]);
            atomicAdd(&ssum[lc + 1], lsum[nt][1]);
            atomicAdd(&ssq[lc],      lsq[nt][0]);
            atomicAdd(&ssq[lc + 1],  lsq[nt][1]);
        }
        __syncthreads();
        if (tid < BN) {
            atomicAdd(&g_sum[col0 + tid], ssum[tid]);
            atomicAdd(&g_sq[col0 + tid],  ssq[tid]);
        }
    }
}

static void gemm_launch(int epi, const __half* A, const __half* Wt, const float* bias,
                        void* C, float* Cb, int M, const int* z, const float* emb) {
    dim3 grid(2, (M + BM - 1) / BM);
    switch (epi) {
        case 0: k_gemm<0><<<grid, 256, SMEM_BYTES>>>(A, Wt, bias, C, Cb, M, z, emb); break;
        case 1: k_gemm<1><<<grid, 256, SMEM_BYTES>>>(A, Wt, bias, C, Cb, M, z, emb); break;
        case 2: k_gemm<2><<<grid, 256, SMEM_BYTES>>>(A, Wt, bias, C, Cb, M, z, emb); break;
        case 3: k_gemm<3><<<grid, 256, SMEM_BYTES>>>(A, Wt, bias, C, Cb, M, z, emb); break;
        case 4: k_gemm<4><<<grid, 256, SMEM_BYTES>>>(A, Wt, bias, C, Cb, M, z, emb); break;
    }
}

// ---------------------------------------------------------------------------
extern "C" void kernel_launch(void* const* d_in, const int* in_sizes, int n_in,
                              void* d_out, int out_size) {
    const int*   z     = (const int*)d_in[0];
    const float* ch    = (const float*)d_in[1];
    const float* fc    = (const float*)d_in[2];
    const int*   ei    = (const int*)d_in[3];
    const float* ea    = (const float*)d_in[4];
    const int*   batch = (const int*)d_in[5];

    int o = (in_sizes[6] == 1) ? 7 : 6;
    const float* atom_emb = (const float*)d_in[o + 0];
    const float* nW1   = (const float*)d_in[o + 1];
    const float* nb1   = (const float*)d_in[o + 2];
    const float* nW2   = (const float*)d_in[o + 3];
    const float* nb2   = (const float*)d_in[o + 4];
    const float* eW1   = (const float*)d_in[o + 5];
    const float* eb1   = (const float*)d_in[o + 6];
    const float* eW2   = (const float*)d_in[o + 7];
    const float* eb2   = (const float*)d_in[o + 8];
    const float* mW1   = (const float*)d_in[o + 9];
    const float* mb1   = (const float*)d_in[o + 10];
    const float* mW2   = (const float*)d_in[o + 11];
    const float* mb2   = (const float*)d_in[o + 12];
    const float* gamma = (const float*)d_in[o + 13];
    const float* beta  = (const float*)d_in[o + 14];
    const float* pW    = (const float*)d_in[o + 15];
    const float* pb    = (const float*)d_in[o + 16];

    int N = in_sizes[0];
    int E = in_sizes[3] / 2;
    int G = out_size / D0;
    const int* src = ei;
    const int* dst = ei + E;

    __half *ph16, *pt16, *pa16, *pe16, *px16, *pp16, *pw16;
    float *pagg, *ppool, *pcnt;
    cudaGetSymbolAddress((void**)&ph16, g_h16);
    cudaGetSymbolAddress((void**)&pt16, g_t16);
    cudaGetSymbolAddress((void**)&pa16, g_a16);
    cudaGetSymbolAddress((void**)&pe16, g_e16);
    cudaGetSymbolAddress((void**)&px16, g_x16);
    cudaGetSymbolAddress((void**)&pp16, g_p16);
    cudaGetSymbolAddress((void**)&pw16, g_w16);
    cudaGetSymbolAddress((void**)&pagg, g_agg);
    cudaGetSymbolAddress((void**)&ppool, g_pool);
    cudaGetSymbolAddress((void**)&pcnt, g_cnt);

    const size_t WSZ = (size_t)DP * DP;
    int wgrid = (DP * DP + 255) / 256;

    // convert + transpose + pad all weights to fp16 [n][k]
    k_wcvt<<<wgrid, 256>>>(nW2, pw16 + 0 * WSZ);
    k_wcvt<<<wgrid, 256>>>(eW2, pw16 + 1 * WSZ);
    for (int l = 0; l < NLAYER; l++) {
        k_wcvt<<<wgrid, 256>>>(mW1 + (size_t)l * D0 * D0, pw16 + (2 + l) * WSZ);
        k_wcvt<<<wgrid, 256>>>(mW2 + (size_t)l * D0 * D0, pw16 + (7 + l) * WSZ);
    }
    k_wcvt<<<wgrid, 256>>>(pW, pw16 + 12 * WSZ);

    int n4 = N * 80;
    int e4 = E * 80;

    // node encoder: h16 = atom_emb[z] + relu(attr@nW1+nb1)@nW2 + nb2; agg = h fp32
    k_node_hidden<<<(n4 + 255) / 256, 256>>>(ch, fc, nW1, nb1, px16, N);
    gemm_launch(2, px16, pw16 + 0 * WSZ, nb2, ph16, pagg, N, z, atom_emb);

    // edge encoder: e16 = relu(edge_attr@eW1+eb1)@eW2 + eb2
    k_edge_hidden<<<(e4 + 255) / 256, 256>>>(ea, eW1, eb1, px16, E);
    gemm_launch(0, px16, pw16 + 1 * WSZ, eb2, pe16, nullptr, E, nullptr, nullptr);

    for (int l = 0; l < NLAYER; l++) {
        // agg (= h) += sum relu(h[src]+e)
        k_scatter<<<(E * 32 + 255) / 256, 256>>>(src, dst, E);
        k_cvt<<<(n4 + 255) / 256, 256>>>(N);
        // t16 = relu(a16 @ mW1 + mb1)
        gemm_launch(1, pa16, pw16 + (2 + l) * WSZ, mb1 + (size_t)l * D0,
                    pt16, nullptr, N, nullptr, nullptr);
        // agg = t16 @ mW2 + mb2 (fp32) + fused column stats
        k_zerostats<<<1, DP>>>();
        gemm_launch(3, pt16, pw16 + (7 + l) * WSZ, mb2 + (size_t)l * D0,
                    pagg, nullptr, N, nullptr, nullptr);
        k_bnprep<<<1, DP>>>(gamma + (size_t)l * D0, beta + (size_t)l * D0, 1.f / (float)N);
        k_bnapply<<<(n4 + 255) / 256, 256>>>(N);  // h16 = relu(bn(agg)); agg = h
    }

    // mean pooling + projection
    int g4 = G * 80;
    k_fill0<<<(g4 + 255) / 256, 256>>>((float4*)ppool, g4);
    k_fill0<<<(G / 4 + 255) / 256, 256>>>((float4*)pcnt, G / 4);
    k_count<<<(N + 255) / 256, 256>>>(batch, N);
    k_pool<<<(N * 32 + 255) / 256, 256>>>(batch, N);
    k_scalepool<<<(g4 + 255) / 256, 256>>>(G);
    gemm_launch(4, pp16, pw16 + 12 * WSZ, pb, d_out, nullptr, G, nullptr, nullptr);
}